// round 12
// baseline (speedup 1.0000x reference)
#include <cuda_runtime.h>
#include <math.h>
#include <stdint.h>

#define BATCH 8
#define NPTS 2048
#define GRIDX 74              // blocks per batch; 74*8 = 592 = 148 SMs * 4
#define WSLOTS (GRIDX * 8)    // 592 warp-slots per batch
#define UNITS 512             // 4-row units per batch

__device__ float g_part[BATCH][GRIDX][12];
__device__ unsigned int g_count[BATCH];   // zero-init; reset each call

// ---------------------------------------------------------------------------
// Fused kernel. grid = (74, 8), block = 256 (8 warps). Balanced partition:
// warp-slot g (0..591) is busy iff floor((g+1)*512/592) > floor(g*512/592);
// busy slot processes unit lo = g*512/592 = g*32/37 (rows 4*lo .. 4*lo+3).
// Every SM hosts exactly 4 blocks -> 27-28 busy warps (vs 24-32 before).
// Last block per batch reduces partials -> means, S, polar, R, t.
// ---------------------------------------------------------------------------
__global__ void __launch_bounds__(256, 4) fused_kernel(
    const float* __restrict__ P,
    const float* __restrict__ Q,
    const float* __restrict__ M,
    float* __restrict__ out) {
    const int b = blockIdx.y;
    const int tid = threadIdx.x;
    const int warp = tid >> 5;
    const int lane = tid & 31;

    __shared__ float p0[NPTS], p1[NPTS], p2[NPTS];
    __shared__ float sacc[8][12];
    __shared__ float warpSums[8][6];
    __shared__ float sTv[12];
    __shared__ int sIsLast;

    const float* Pb = P + (size_t)b * NPTS * 3;
    const float* Qb = Q + (size_t)b * NPTS * 3;

    for (int i = tid; i < NPTS * 3; i += 256) {
        float v = Pb[i];
        int pt = i / 3, c = i - pt * 3;
        float* dst = (c == 0) ? p0 : (c == 1) ? p1 : p2;
        dst[pt] = v;
    }
    __syncthreads();

    // balanced warp-slot -> unit mapping
    const int g = blockIdx.x * 8 + warp;               // 0..591
    const int lo = (g * 32) / 37;                      // = g*512/592
    const int busy = (((g + 1) * 32) / 37) > lo;
    const int n0 = lo * 4;

    float d[12];
    #pragma unroll
    for (int i = 0; i < 12; i++) d[i] = 0.f;

    if (busy) {
        const float4* Rbase = reinterpret_cast<const float4*>(
            M + (size_t)b * NPTS * NPTS + (size_t)n0 * NPTS);
        #pragma unroll 4
        for (int it = 0; it < NPTS / 128; it++) {     // 16 iterations
            int m4 = it * 32 + lane;
            float4 mv0 = __ldcs(&Rbase[m4]);                      // row n0
            float4 mv1 = __ldcs(&Rbase[m4 + 1 * (NPTS / 4)]);     // row n0+1
            float4 mv2 = __ldcs(&Rbase[m4 + 2 * (NPTS / 4)]);     // row n0+2
            float4 mv3 = __ldcs(&Rbase[m4 + 3 * (NPTS / 4)]);     // row n0+3
            int m = m4 * 4;
            float4 a  = *reinterpret_cast<const float4*>(&p0[m]);
            float4 bb = *reinterpret_cast<const float4*>(&p1[m]);
            float4 c  = *reinterpret_cast<const float4*>(&p2[m]);
            d[0]  += mv0.x * a.x  + mv0.y * a.y  + mv0.z * a.z  + mv0.w * a.w;
            d[1]  += mv0.x * bb.x + mv0.y * bb.y + mv0.z * bb.z + mv0.w * bb.w;
            d[2]  += mv0.x * c.x  + mv0.y * c.y  + mv0.z * c.z  + mv0.w * c.w;
            d[3]  += mv1.x * a.x  + mv1.y * a.y  + mv1.z * a.z  + mv1.w * a.w;
            d[4]  += mv1.x * bb.x + mv1.y * bb.y + mv1.z * bb.z + mv1.w * bb.w;
            d[5]  += mv1.x * c.x  + mv1.y * c.y  + mv1.z * c.z  + mv1.w * c.w;
            d[6]  += mv2.x * a.x  + mv2.y * a.y  + mv2.z * a.z  + mv2.w * a.w;
            d[7]  += mv2.x * bb.x + mv2.y * bb.y + mv2.z * bb.z + mv2.w * bb.w;
            d[8]  += mv2.x * c.x  + mv2.y * c.y  + mv2.z * c.z  + mv2.w * c.w;
            d[9]  += mv3.x * a.x  + mv3.y * a.y  + mv3.z * a.z  + mv3.w * a.w;
            d[10] += mv3.x * bb.x + mv3.y * bb.y + mv3.z * bb.z + mv3.w * bb.w;
            d[11] += mv3.x * c.x  + mv3.y * c.y  + mv3.z * c.z  + mv3.w * c.w;
        }
    }

    #pragma unroll
    for (int off = 16; off > 0; off >>= 1) {
        #pragma unroll
        for (int j = 0; j < 12; j++)
            d[j] += __shfl_xor_sync(0xffffffffu, d[j], off);
    }

    if (lane == 0) {
        // idle warps have d == 0; q values are harmless multipliers
        const float* q = Qb + n0 * 3;
        float q0x = q[0], q0y = q[1],  q0z = q[2];
        float q1x = q[3], q1y = q[4],  q1z = q[5];
        float q2x = q[6], q2y = q[7],  q2z = q[8];
        float q3x = q[9], q3y = q[10], q3z = q[11];
        sacc[warp][0] = d[0] * q0x + d[3] * q1x + d[6] * q2x + d[9]  * q3x;
        sacc[warp][1] = d[0] * q0y + d[3] * q1y + d[6] * q2y + d[9]  * q3y;
        sacc[warp][2] = d[0] * q0z + d[3] * q1z + d[6] * q2z + d[9]  * q3z;
        sacc[warp][3] = d[1] * q0x + d[4] * q1x + d[7] * q2x + d[10] * q3x;
        sacc[warp][4] = d[1] * q0y + d[4] * q1y + d[7] * q2y + d[10] * q3y;
        sacc[warp][5] = d[1] * q0z + d[4] * q1z + d[7] * q2z + d[10] * q3z;
        sacc[warp][6] = d[2] * q0x + d[5] * q1x + d[8] * q2x + d[11] * q3x;
        sacc[warp][7] = d[2] * q0y + d[5] * q1y + d[8] * q2y + d[11] * q3y;
        sacc[warp][8] = d[2] * q0z + d[5] * q1z + d[8] * q2z + d[11] * q3z;
        sacc[warp][9]  = d[0] + d[3] + d[6] + d[9];
        sacc[warp][10] = d[1] + d[4] + d[7] + d[10];
        sacc[warp][11] = d[2] + d[5] + d[8] + d[11];
    }
    __syncthreads();
    if (tid < 12) {
        float s = 0.f;
        #pragma unroll
        for (int w = 0; w < 8; w++) s += sacc[w][tid];
        g_part[b][blockIdx.x][tid] = s;
    }
    __threadfence();
    __syncthreads();

    // ---------------- Phase 2: last block of this batch finishes ----------------
    if (tid == 0) {
        unsigned int old = atomicAdd(&g_count[b], 1u);
        sIsLast = (old == GRIDX - 1u) ? 1 : 0;
    }
    __syncthreads();
    if (!sIsLast) return;
    __threadfence();   // acquire: make other blocks' g_part writes visible

    // --- means: P from smem, Q via float4 triples from global ---
    float sp0 = 0.f, sp1 = 0.f, sp2 = 0.f;
    for (int n = tid; n < NPTS; n += 256) {
        sp0 += p0[n]; sp1 += p1[n]; sp2 += p2[n];
    }
    float sq0 = 0.f, sq1 = 0.f, sq2 = 0.f;
    const float4* Q4 = reinterpret_cast<const float4*>(Qb);
    #pragma unroll
    for (int t = 0; t < 2; t++) {
        int tr = tid + t * 256;               // triple index, 512 total
        float4 A = Q4[tr * 3 + 0];
        float4 Bv = Q4[tr * 3 + 1];
        float4 C = Q4[tr * 3 + 2];
        sq0 += A.x + A.w + Bv.z + C.y;
        sq1 += A.y + Bv.x + Bv.w + C.z;
        sq2 += A.z + Bv.y + C.x + C.w;
    }
    #pragma unroll
    for (int off = 16; off > 0; off >>= 1) {
        sp0 += __shfl_xor_sync(0xffffffffu, sp0, off);
        sp1 += __shfl_xor_sync(0xffffffffu, sp1, off);
        sp2 += __shfl_xor_sync(0xffffffffu, sp2, off);
        sq0 += __shfl_xor_sync(0xffffffffu, sq0, off);
        sq1 += __shfl_xor_sync(0xffffffffu, sq1, off);
        sq2 += __shfl_xor_sync(0xffffffffu, sq2, off);
    }
    if (lane == 0) {
        warpSums[warp][0] = sp0; warpSums[warp][1] = sp1; warpSums[warp][2] = sp2;
        warpSums[warp][3] = sq0; warpSums[warp][4] = sq1; warpSums[warp][5] = sq2;
    }

    // --- warp 0 reduces the GRIDX x 12 partials ---
    if (warp == 0) {
        float Tv[12];
        #pragma unroll
        for (int j = 0; j < 12; j++) Tv[j] = 0.f;
        for (int r = lane; r < GRIDX; r += 32) {
            const float* row = g_part[b][r];
            #pragma unroll
            for (int j = 0; j < 12; j++) Tv[j] += row[j];
        }
        #pragma unroll
        for (int off = 16; off > 0; off >>= 1) {
            #pragma unroll
            for (int j = 0; j < 12; j++)
                Tv[j] += __shfl_xor_sync(0xffffffffu, Tv[j], off);
        }
        if (lane == 0) {
            #pragma unroll
            for (int j = 0; j < 12; j++) sTv[j] = Tv[j];
        }
    }
    __syncthreads();

    if (tid == 0) {
        g_count[b] = 0u;   // reset for next graph replay

        float mS[6];
        #pragma unroll
        for (int j = 0; j < 6; j++) {
            float s = 0.f;
            #pragma unroll
            for (int w = 0; w < 8; w++) s += warpSums[w][j];
            mS[j] = s;
        }
        const float inv = 1.0f / (float)NPTS;
        float mp0 = mS[0] * inv, mp1 = mS[1] * inv, mp2 = mS[2] * inv;
        float mq0 = mS[3] * inv, mq1 = mS[4] * inv, mq2 = mS[5] * inv;

        float v0 = sTv[9], v1 = sTv[10], v2 = sTv[11];
        float X[9];
        X[0] = sTv[0] - v0 * mq0; X[1] = sTv[1] - v0 * mq1; X[2] = sTv[2] - v0 * mq2;
        X[3] = sTv[3] - v1 * mq0; X[4] = sTv[4] - v1 * mq1; X[5] = sTv[5] - v1 * mq2;
        X[6] = sTv[6] - v2 * mq0; X[7] = sTv[7] - v2 * mq1; X[8] = sTv[8] - v2 * mq2;

        // Newton polar iteration (det-scaled): X -> 0.5*(g*X + sgn*g^2*cof(X))
        #pragma unroll
        for (int it = 0; it < 12; it++) {
            float C[9];
            C[0] = X[4] * X[8] - X[5] * X[7];
            C[1] = X[5] * X[6] - X[3] * X[8];
            C[2] = X[3] * X[7] - X[4] * X[6];
            C[3] = X[2] * X[7] - X[1] * X[8];
            C[4] = X[0] * X[8] - X[2] * X[6];
            C[5] = X[1] * X[6] - X[0] * X[7];
            C[6] = X[1] * X[5] - X[2] * X[4];
            C[7] = X[2] * X[3] - X[0] * X[5];
            C[8] = X[0] * X[4] - X[1] * X[3];
            float det = X[0] * C[0] + X[1] * C[1] + X[2] * C[2];
            float g2 = rcbrtf(fabsf(det));
            float g2s = copysignf(g2 * g2, det);
            #pragma unroll
            for (int i = 0; i < 9; i++) X[i] = 0.5f * (g2 * X[i] + g2s * C[i]);
        }

        float* Rout = out + b * 9;
        float* tout = out + BATCH * 9 + b * 3;
        float mp[3] = {mp0, mp1, mp2};
        float mq[3] = {mq0, mq1, mq2};
        #pragma unroll
        for (int i = 0; i < 3; i++) {
            float ti = mq[i];
            #pragma unroll
            for (int j = 0; j < 3; j++) {
                float r = X[j * 3 + i];        // R = polar^T
                Rout[i * 3 + j] = r;
                ti -= r * mp[j];
            }
            tout[i] = ti;
        }
    }
}

// ---------------------------------------------------------------------------
extern "C" void kernel_launch(void* const* d_in, const int* in_sizes, int n_in,
                              void* d_out, int out_size) {
    const float* P = (const float*)d_in[0];   // Ppc [8,2048,3]
    const float* Q = (const float*)d_in[1];   // Qpc [8,2048,3]
    const float* M = (const float*)d_in[2];   // M   [8,2048,2048]
    float* out = (float*)d_out;               // 72 R + 24 t

    fused_kernel<<<dim3(GRIDX, BATCH), 256>>>(P, Q, M, out);
}

// round 13
// speedup vs baseline: 1.0634x; 1.0634x over previous
#include <cuda_runtime.h>
#include <math.h>
#include <stdint.h>

#define BATCH 8
#define NPTS 2048
#define GRIDX 64               // blocks per batch (32 rows each)
#define ROWS_PB 32
#define STAGE_FLOATS NPTS      // 1 row = 8 KB per stage
#define STAGE_BYTES (STAGE_FLOATS * 4)
#define NSTAGES 6              // 48 KB ring; 4 fetches in flight at steady state
#define NIT ROWS_PB            // 32 iterations

__device__ float g_part[BATCH][GRIDX][12];
__device__ unsigned int g_count[BATCH];   // zero-init; reset each call

__device__ __forceinline__ uint32_t smem_u32(const void* p) {
    return (uint32_t)__cvta_generic_to_shared(p);
}
__device__ __forceinline__ void mbar_init(uint32_t mbar, uint32_t count) {
    asm volatile("mbarrier.init.shared.b64 [%0], %1;" :: "r"(mbar), "r"(count) : "memory");
}
__device__ __forceinline__ void mbar_expect_tx(uint32_t mbar, uint32_t bytes) {
    asm volatile("mbarrier.arrive.expect_tx.shared::cta.b64 _, [%0], %1;"
                 :: "r"(mbar), "r"(bytes) : "memory");
}
__device__ __forceinline__ void mbar_wait(uint32_t mbar, uint32_t parity) {
    asm volatile(
        "{\n\t.reg .pred P1;\n\t"
        "WAIT_%=:\n\t"
        "mbarrier.try_wait.parity.acquire.cta.shared::cta.b64 P1, [%0], %1, 0x989680;\n\t"
        "@P1 bra.uni DONE_%=;\n\t"
        "bra.uni WAIT_%=;\n\t"
        "DONE_%=:\n\t}"
        :: "r"(mbar), "r"(parity) : "memory");
}
__device__ __forceinline__ void tma_bulk_1d(uint32_t dst, const void* src,
                                            uint32_t bytes, uint32_t mbar) {
    asm volatile(
        "cp.async.bulk.shared::cta.global.mbarrier::complete_tx::bytes [%0], [%1], %2, [%3];"
        :: "r"(dst), "l"(src), "r"(bytes), "r"(mbar) : "memory");
}

// ---------------------------------------------------------------------------
// grid = (GRIDX, BATCH), block = 256 (8 warps). TMA bulk stages one 8KB row of
// M per stage through a 6-deep dynamic-smem ring (4 rows in flight during
// compute). Thread t owns columns {4t..4t+3} and {1024+4t..1024+4t+3}
// (conflict-free LDS.128). Accumulates wA/wB[4][3] = sum_n M[n,c] q[n,:] and
// csA/csB[4] = sum_n M[n,c]; contracts with P once at the end.
// Last block per batch reduces partials -> means, S, polar, R, t.
// ---------------------------------------------------------------------------
__global__ void __launch_bounds__(256, 4) fused_kernel(
    const float* __restrict__ P,
    const float* __restrict__ Q,
    const float* __restrict__ M,
    float* __restrict__ out) {
    extern __shared__ __align__(16) float ring[];   // NSTAGES * STAGE_FLOATS

    const int b = blockIdx.y;
    const int rowblk = blockIdx.x;
    const int tid = threadIdx.x;
    const int warp = tid >> 5;
    const int lane = tid & 31;

    __shared__ __align__(8) unsigned long long mbars[NSTAGES];
    __shared__ float sQ[ROWS_PB * 3];
    __shared__ float sacc[8][12];
    __shared__ float warpSums[8][6];
    __shared__ float sTv[12];
    __shared__ int sIsLast;

    const float* Pb = P + (size_t)b * NPTS * 3;
    const float* Qb = Q + (size_t)b * NPTS * 3;
    const char* gsrc = (const char*)(M + (size_t)b * NPTS * NPTS
                                       + (size_t)rowblk * ROWS_PB * NPTS);

    if (tid < ROWS_PB * 3) sQ[tid] = Qb[rowblk * ROWS_PB * 3 + tid];
    if (tid == 0) {
        #pragma unroll
        for (int s = 0; s < NSTAGES; s++) mbar_init(smem_u32(&mbars[s]), 1);
    }
    __syncthreads();

    const uint32_t rbase = smem_u32(ring);
    uint32_t mb[NSTAGES];
    #pragma unroll
    for (int s = 0; s < NSTAGES; s++) mb[s] = smem_u32(&mbars[s]);

    // prologue: fill stages 0..NSTAGES-2
    if (tid == 0) {
        #pragma unroll
        for (int s = 0; s < NSTAGES - 1; s++) {
            mbar_expect_tx(mb[s], STAGE_BYTES);
            tma_bulk_1d(rbase + s * STAGE_BYTES, gsrc + (size_t)s * STAGE_BYTES,
                        STAGE_BYTES, mb[s]);
        }
    }

    // thread's two column groups (conflict-free LDS.128)
    const int cA = tid * 4;
    const int cB = 1024 + tid * 4;

    float wA[4][3], wB[4][3], csA[4], csB[4];
    #pragma unroll
    for (int k = 0; k < 4; k++) {
        wA[k][0] = wA[k][1] = wA[k][2] = 0.f; csA[k] = 0.f;
        wB[k][0] = wB[k][1] = wB[k][2] = 0.f; csB[k] = 0.f;
    }

    #pragma unroll
    for (int it = 0; it < NIT; it++) {
        const int slot = it % NSTAGES;
        const uint32_t parity = (it / NSTAGES) & 1;
        mbar_wait(mb[slot], parity);

        const float* st = ring + slot * STAGE_FLOATS;
        float4 ma = *reinterpret_cast<const float4*>(st + cA);
        float4 mbv = *reinterpret_cast<const float4*>(st + cB);
        float q0 = sQ[it * 3 + 0];
        float q1 = sQ[it * 3 + 1];
        float q2 = sQ[it * 3 + 2];
        float am[4] = {ma.x, ma.y, ma.z, ma.w};
        float bm[4] = {mbv.x, mbv.y, mbv.z, mbv.w};
        #pragma unroll
        for (int k = 0; k < 4; k++) {
            wA[k][0] += am[k] * q0; wA[k][1] += am[k] * q1; wA[k][2] += am[k] * q2;
            csA[k] += am[k];
            wB[k][0] += bm[k] * q0; wB[k][1] += bm[k] * q1; wB[k][2] += bm[k] * q2;
            csB[k] += bm[k];
        }
        __syncthreads();   // slot `it % NSTAGES` now recyclable
        if (tid == 0 && it + NSTAGES - 1 < NIT) {
            const int ns = (it + NSTAGES - 1) % NSTAGES;
            mbar_expect_tx(mb[ns], STAGE_BYTES);
            tma_bulk_1d(rbase + ns * STAGE_BYTES,
                        gsrc + (size_t)(it + NSTAGES - 1) * STAGE_BYTES,
                        STAGE_BYTES, mb[ns]);
        }
    }

    // contract with P:  T[i][j] = sum_k P[col_k][i] * w[k][j];  v[i] = sum P*cs
    float T[9] = {0,0,0,0,0,0,0,0,0};
    float v[3] = {0,0,0};
    {
        const float4* pa = reinterpret_cast<const float4*>(Pb + (size_t)cA * 3);
        float4 f0 = __ldg(pa + 0), f1 = __ldg(pa + 1), f2 = __ldg(pa + 2);
        float px[4] = {f0.x, f0.w, f1.z, f2.y};
        float py[4] = {f0.y, f1.x, f1.w, f2.z};
        float pz[4] = {f0.z, f1.y, f2.x, f2.w};
        #pragma unroll
        for (int k = 0; k < 4; k++) {
            T[0] += px[k] * wA[k][0]; T[1] += px[k] * wA[k][1]; T[2] += px[k] * wA[k][2];
            T[3] += py[k] * wA[k][0]; T[4] += py[k] * wA[k][1]; T[5] += py[k] * wA[k][2];
            T[6] += pz[k] * wA[k][0]; T[7] += pz[k] * wA[k][1]; T[8] += pz[k] * wA[k][2];
            v[0] += px[k] * csA[k];   v[1] += py[k] * csA[k];   v[2] += pz[k] * csA[k];
        }
        const float4* pb = reinterpret_cast<const float4*>(Pb + (size_t)cB * 3);
        float4 g0 = __ldg(pb + 0), g1 = __ldg(pb + 1), g2 = __ldg(pb + 2);
        float qx[4] = {g0.x, g0.w, g1.z, g2.y};
        float qy[4] = {g0.y, g1.x, g1.w, g2.z};
        float qz[4] = {g0.z, g1.y, g2.x, g2.w};
        #pragma unroll
        for (int k = 0; k < 4; k++) {
            T[0] += qx[k] * wB[k][0]; T[1] += qx[k] * wB[k][1]; T[2] += qx[k] * wB[k][2];
            T[3] += qy[k] * wB[k][0]; T[4] += qy[k] * wB[k][1]; T[5] += qy[k] * wB[k][2];
            T[6] += qz[k] * wB[k][0]; T[7] += qz[k] * wB[k][1]; T[8] += qz[k] * wB[k][2];
            v[0] += qx[k] * csB[k];   v[1] += qy[k] * csB[k];   v[2] += qz[k] * csB[k];
        }
    }

    float r12[12] = {T[0],T[1],T[2],T[3],T[4],T[5],T[6],T[7],T[8],v[0],v[1],v[2]};
    #pragma unroll
    for (int off = 16; off > 0; off >>= 1) {
        #pragma unroll
        for (int j = 0; j < 12; j++)
            r12[j] += __shfl_xor_sync(0xffffffffu, r12[j], off);
    }
    if (lane == 0) {
        #pragma unroll
        for (int j = 0; j < 12; j++) sacc[warp][j] = r12[j];
    }
    __syncthreads();
    if (tid < 12) {
        float s = 0.f;
        #pragma unroll
        for (int wv = 0; wv < 8; wv++) s += sacc[wv][tid];
        g_part[b][rowblk][tid] = s;
    }
    __threadfence();
    __syncthreads();

    // ---------------- last block of this batch finishes ----------------
    if (tid == 0) {
        unsigned int old = atomicAdd(&g_count[b], 1u);
        sIsLast = (old == GRIDX - 1u) ? 1 : 0;
    }
    __syncthreads();
    if (!sIsLast) return;
    __threadfence();

    // --- means of P and Q via float4 triples from global ---
    float sp0 = 0.f, sp1 = 0.f, sp2 = 0.f;
    float sq0 = 0.f, sq1 = 0.f, sq2 = 0.f;
    const float4* P4 = reinterpret_cast<const float4*>(Pb);
    const float4* Q4 = reinterpret_cast<const float4*>(Qb);
    #pragma unroll
    for (int t = 0; t < 2; t++) {
        int tr = tid + t * 256;
        float4 A = P4[tr * 3 + 0];
        float4 Bv = P4[tr * 3 + 1];
        float4 C = P4[tr * 3 + 2];
        sp0 += A.x + A.w + Bv.z + C.y;
        sp1 += A.y + Bv.x + Bv.w + C.z;
        sp2 += A.z + Bv.y + C.x + C.w;
        float4 A2 = Q4[tr * 3 + 0];
        float4 B2 = Q4[tr * 3 + 1];
        float4 C2 = Q4[tr * 3 + 2];
        sq0 += A2.x + A2.w + B2.z + C2.y;
        sq1 += A2.y + B2.x + B2.w + C2.z;
        sq2 += A2.z + B2.y + C2.x + C2.w;
    }
    #pragma unroll
    for (int off = 16; off > 0; off >>= 1) {
        sp0 += __shfl_xor_sync(0xffffffffu, sp0, off);
        sp1 += __shfl_xor_sync(0xffffffffu, sp1, off);
        sp2 += __shfl_xor_sync(0xffffffffu, sp2, off);
        sq0 += __shfl_xor_sync(0xffffffffu, sq0, off);
        sq1 += __shfl_xor_sync(0xffffffffu, sq1, off);
        sq2 += __shfl_xor_sync(0xffffffffu, sq2, off);
    }
    if (lane == 0) {
        warpSums[warp][0] = sp0; warpSums[warp][1] = sp1; warpSums[warp][2] = sp2;
        warpSums[warp][3] = sq0; warpSums[warp][4] = sq1; warpSums[warp][5] = sq2;
    }

    if (warp == 0) {
        float Tv[12];
        #pragma unroll
        for (int j = 0; j < 12; j++) Tv[j] = 0.f;
        #pragma unroll
        for (int r = 0; r < GRIDX / 32; r++) {
            const float* row = g_part[b][lane + r * 32];
            #pragma unroll
            for (int j = 0; j < 12; j++) Tv[j] += row[j];
        }
        #pragma unroll
        for (int off = 16; off > 0; off >>= 1) {
            #pragma unroll
            for (int j = 0; j < 12; j++)
                Tv[j] += __shfl_xor_sync(0xffffffffu, Tv[j], off);
        }
        if (lane == 0) {
            #pragma unroll
            for (int j = 0; j < 12; j++) sTv[j] = Tv[j];
        }
    }
    __syncthreads();

    if (tid == 0) {
        g_count[b] = 0u;

        float mS[6];
        #pragma unroll
        for (int j = 0; j < 6; j++) {
            float s = 0.f;
            #pragma unroll
            for (int wv = 0; wv < 8; wv++) s += warpSums[wv][j];
            mS[j] = s;
        }
        const float inv = 1.0f / (float)NPTS;
        float mp0 = mS[0] * inv, mp1 = mS[1] * inv, mp2 = mS[2] * inv;
        float mq0 = mS[3] * inv, mq1 = mS[4] * inv, mq2 = mS[5] * inv;

        float v0 = sTv[9], v1 = sTv[10], v2 = sTv[11];
        float X[9];
        X[0] = sTv[0] - v0 * mq0; X[1] = sTv[1] - v0 * mq1; X[2] = sTv[2] - v0 * mq2;
        X[3] = sTv[3] - v1 * mq0; X[4] = sTv[4] - v1 * mq1; X[5] = sTv[5] - v1 * mq2;
        X[6] = sTv[6] - v2 * mq0; X[7] = sTv[7] - v2 * mq1; X[8] = sTv[8] - v2 * mq2;

        // Newton polar iteration (det-scaled): X -> 0.5*(g*X + sgn*g^2*cof(X))
        #pragma unroll
        for (int itn = 0; itn < 10; itn++) {
            float C[9];
            C[0] = X[4] * X[8] - X[5] * X[7];
            C[1] = X[5] * X[6] - X[3] * X[8];
            C[2] = X[3] * X[7] - X[4] * X[6];
            C[3] = X[2] * X[7] - X[1] * X[8];
            C[4] = X[0] * X[8] - X[2] * X[6];
            C[5] = X[1] * X[6] - X[0] * X[7];
            C[6] = X[1] * X[5] - X[2] * X[4];
            C[7] = X[2] * X[3] - X[0] * X[5];
            C[8] = X[0] * X[4] - X[1] * X[3];
            float det = X[0] * C[0] + X[1] * C[1] + X[2] * C[2];
            float g = rcbrtf(fabsf(det));
            float g2s = copysignf(g * g, det);
            #pragma unroll
            for (int i = 0; i < 9; i++) X[i] = 0.5f * (g * X[i] + g2s * C[i]);
        }

        float* Rout = out + b * 9;
        float* tout = out + BATCH * 9 + b * 3;
        float mp[3] = {mp0, mp1, mp2};
        float mq[3] = {mq0, mq1, mq2};
        #pragma unroll
        for (int i = 0; i < 3; i++) {
            float ti = mq[i];
            #pragma unroll
            for (int j = 0; j < 3; j++) {
                float r = X[j * 3 + i];   // R = polar^T
                Rout[i * 3 + j] = r;
                ti -= r * mp[j];
            }
            tout[i] = ti;
        }
    }
}

// ---------------------------------------------------------------------------
extern "C" void kernel_launch(void* const* d_in, const int* in_sizes, int n_in,
                              void* d_out, int out_size) {
    const float* P = (const float*)d_in[0];   // Ppc [8,2048,3]
    const float* Q = (const float*)d_in[1];   // Qpc [8,2048,3]
    const float* M = (const float*)d_in[2];   // M   [8,2048,2048]
    float* out = (float*)d_out;               // 72 R + 24 t

    const int dynSmem = NSTAGES * STAGE_BYTES;   // 48 KB
    static bool attrSet = false;
    if (!attrSet) {
        cudaFuncSetAttribute(fused_kernel,
                             cudaFuncAttributeMaxDynamicSharedMemorySize, dynSmem);
        attrSet = true;
    }
    fused_kernel<<<dim3(GRIDX, BATCH), 256, dynSmem>>>(P, Q, M, out);
}